// round 3
// baseline (speedup 1.0000x reference)
#include <cuda_runtime.h>

// SpatialDeformer3D: out[b,h,w,d] = trilinear sample of X[b,:,:,:,0] at
// (y,x,z) = (h,w,d) + deformation[b,h,w,d,(1,0,2)]
//
// Shapes (fixed by the reference setup_inputs):
//   X:           (2, 160, 192, 160, 2)  float32
//   deformation: (2, 160, 192, 160, 3)  float32
//   out:         (2, 160, 192, 160, 1)  float32

#define BB 2
#define HH 160
#define WW 192
#define DD 160
#define WD (WW * DD)          // 30720
#define NN (HH * WD)          // 4915200
#define TOTAL (BB * NN)       // 9830400

__global__ __launch_bounds__(256) void deform3d_kernel(
    const float* __restrict__ X,     // (B,H,W,D,2)
    const float* __restrict__ def,   // (B,H,W,D,3)
    float* __restrict__ out)         // (B,H,W,D,1)
{
    int idx = blockIdx.x * blockDim.x + threadIdx.x;
    if (idx >= TOTAL) return;

    // Decompose idx -> (b, h, w, d); d fastest => coalesced def/out access.
    int b = idx / NN;
    int n = idx - b * NN;
    int h = n / WD;
    int rem = n - h * WD;
    int w = rem / DD;
    int d = rem - w * DD;

    // Deformation: AoS float3, contiguous across threads -> fully coalesced.
    const float* dp = def + (size_t)idx * 3;
    float dx = __ldg(dp + 0);
    float dy = __ldg(dp + 1);
    float dz = __ldg(dp + 2);

    float x = (float)w + dx;   // deformation[...,0] displaces along W
    float y = (float)h + dy;   // deformation[...,1] displaces along H
    float z = (float)d + dz;   // deformation[...,2] displaces along D

    float fx = floorf(x), fy = floorf(y), fz = floorf(z);
    int x0 = (int)fx, y0 = (int)fy, z0 = (int)fz;
    int x1 = x0 + 1, y1 = y0 + 1, z1 = z0 + 1;

    // Clip each corner index independently (reference semantics: weights are
    // computed from the CLIPPED coordinates, so out-of-range dims cancel to 0).
    x0 = min(max(x0, 0), WW - 1);  x1 = min(max(x1, 0), WW - 1);
    y0 = min(max(y0, 0), HH - 1);  y1 = min(max(y1, 0), HH - 1);
    z0 = min(max(z0, 0), DD - 1);  z1 = min(max(z1, 0), DD - 1);

    float x0f = (float)x0, x1f = (float)x1;
    float y0f = (float)y0, y1f = (float)y1;
    float z0f = (float)z0, z1f = (float)z1;

    float wx0 = x1f - x, wx1 = x - x0f;
    float wy0 = y1f - y, wy1 = y - y0f;
    float wz0 = z1f - z, wz1 = z - z0f;

    // Gather 8 taps from channel 0 of X (element stride 2).
    const float* Xb = X + (size_t)b * NN * 2;
    int ry0 = y0 * WD, ry1 = y1 * WD;
    int cx0 = x0 * DD, cx1 = x1 * DD;

    int i00 = (ry0 + cx0) * 2;
    int i01 = (ry0 + cx1) * 2;
    int i10 = (ry1 + cx0) * 2;
    int i11 = (ry1 + cx1) * 2;
    int z0e = z0 * 2, z1e = z1 * 2;

    // Issue all 8 loads up front -> MLP=8 to hide DRAM/L2 latency.
    float p000 = __ldg(Xb + i00 + z0e);
    float p001 = __ldg(Xb + i00 + z1e);
    float p010 = __ldg(Xb + i01 + z0e);
    float p011 = __ldg(Xb + i01 + z1e);
    float p100 = __ldg(Xb + i10 + z0e);
    float p101 = __ldg(Xb + i10 + z1e);
    float p110 = __ldg(Xb + i11 + z0e);
    float p111 = __ldg(Xb + i11 + z1e);

    float r = wy0 * (wx0 * (wz0 * p000 + wz1 * p001) +
                     wx1 * (wz0 * p010 + wz1 * p011)) +
              wy1 * (wx0 * (wz0 * p100 + wz1 * p101) +
                     wx1 * (wz0 * p110 + wz1 * p111));

    out[idx] = r;
}

extern "C" void kernel_launch(void* const* d_in, const int* in_sizes, int n_in,
                              void* d_out, int out_size)
{
    const float* X   = (const float*)d_in[0];
    const float* def = (const float*)d_in[1];
    float* out = (float*)d_out;

    const int threads = 256;
    const int blocks = (TOTAL + threads - 1) / threads;  // 38400
    deform3d_kernel<<<blocks, threads>>>(X, def, out);
}